// round 2
// baseline (speedup 1.0000x reference)
#include <cuda_runtime.h>

// Problem constants
#define BSZ  2
#define HN   12
#define TN   2048
#define DH   64
#define DIMN 768

#define BM 64   // query rows per block
#define BN 32   // key cols per tile

__device__ float g_y[BSZ * TN * DIMN];  // intermediate (B, T, H*D)

// ---------------------------------------------------------------------------
// Flash attention with additive bias, causal mask. fp32.
// Block: 128 threads = 64 rows x 2 half-threads (each owns 32 of 64 dims).
// Grid: (T/BM, B*H)
// ---------------------------------------------------------------------------
__global__ __launch_bounds__(128) void attn_kernel(
    const float* __restrict__ q, const float* __restrict__ k,
    const float* __restrict__ v, const float* __restrict__ bias)
{
    __shared__ float Ks[BN][DH];
    __shared__ float Vs[BN][DH];
    __shared__ float Bs[BM][BN];

    const int m_tile = blockIdx.x;
    const int bh     = blockIdx.y;
    const int tid    = threadIdx.x;
    const int row_l  = tid >> 1;
    const int half   = tid & 1;
    const int row_g  = m_tile * BM + row_l;
    const float SCALE = 0.125f;  // 1/sqrt(64)

    // Load this thread's half of its q row into registers
    const float* qp = q + ((size_t)bh * TN + row_g) * DH + half * 32;
    float qr[32];
#pragma unroll
    for (int j = 0; j < 8; ++j) {
        float4 t4 = reinterpret_cast<const float4*>(qp)[j];
        qr[4*j+0] = t4.x; qr[4*j+1] = t4.y; qr[4*j+2] = t4.z; qr[4*j+3] = t4.w;
    }

    float acc[32];
#pragma unroll
    for (int d = 0; d < 32; ++d) acc[d] = 0.f;
    float mval = -1e30f, lval = 0.f;

    const int ntiles = 2 * m_tile + 2;  // key tiles needed under causal mask
    for (int nt = 0; nt < ntiles; ++nt) {
        // ---- stage K, V tiles (32x64 each) : 4 float4 per thread each ----
        const size_t kvbase = ((size_t)bh * TN + (size_t)nt * BN) * DH;
#pragma unroll
        for (int i = 0; i < 4; ++i) {
            int idx = tid + i * 128;
            reinterpret_cast<float4*>(&Ks[0][0])[idx] =
                reinterpret_cast<const float4*>(k + kvbase)[idx];
            reinterpret_cast<float4*>(&Vs[0][0])[idx] =
                reinterpret_cast<const float4*>(v + kvbase)[idx];
        }
        // ---- stage bias tile (64x32) with float4 loads: 8 f4 per row ----
        // 64 rows * 8 f4 = 512 f4 loads; 4 per thread.
        {
            const float* bbase = bias + ((size_t)bh * TN + (size_t)m_tile * BM) * TN
                                      + (size_t)nt * BN;
#pragma unroll
            for (int i = 0; i < 4; ++i) {
                int idx = tid + i * 128;     // 0..511
                int r = idx >> 3, c4 = idx & 7;
                reinterpret_cast<float4*>(&Bs[r][0])[c4] =
                    reinterpret_cast<const float4*>(bbase + (size_t)r * TN)[c4];
            }
        }
        __syncthreads();

        // ---- scores: partial dots over this thread's 32 dims, pair-reduce ----
        float sc[BN];
#pragma unroll
        for (int i = 0; i < BN; ++i) {
            const float4* kr = reinterpret_cast<const float4*>(&Ks[i][half * 32]);
            float p = 0.f;
#pragma unroll
            for (int jj = 0; jj < 8; ++jj) {
                float4 kv = kr[jj];
                p += qr[4*jj+0] * kv.x + qr[4*jj+1] * kv.y
                   + qr[4*jj+2] * kv.z + qr[4*jj+3] * kv.w;
            }
            p += __shfl_xor_sync(0xffffffffu, p, 1);   // combine halves
            sc[i] = p * SCALE + Bs[row_l][i];
        }
        // causal mask only needed on the last two tiles
        if (nt >= 2 * m_tile) {
#pragma unroll
            for (int i = 0; i < BN; ++i)
                if (nt * BN + i > row_g) sc[i] = -1e30f;
        }

        // ---- online softmax (one rescale per tile) ----
        float tmax = -1e30f;
#pragma unroll
        for (int i = 0; i < BN; ++i) tmax = fmaxf(tmax, sc[i]);
        float mnew = fmaxf(mval, tmax);
        float corr = __expf(mval - mnew);
        float lsum = 0.f;
#pragma unroll
        for (int i = 0; i < BN; ++i) { sc[i] = __expf(sc[i] - mnew); lsum += sc[i]; }
        lval = lval * corr + lsum;
        mval = mnew;
#pragma unroll
        for (int d = 0; d < 32; ++d) acc[d] *= corr;

        // ---- accumulate P @ V over this thread's 32 dims ----
#pragma unroll
        for (int i = 0; i < BN; ++i) {
            const float4* vr = reinterpret_cast<const float4*>(&Vs[i][half * 32]);
            float pi = sc[i];
#pragma unroll
            for (int jj = 0; jj < 8; ++jj) {
                float4 vv = vr[jj];
                acc[4*jj+0] += pi * vv.x;
                acc[4*jj+1] += pi * vv.y;
                acc[4*jj+2] += pi * vv.z;
                acc[4*jj+3] += pi * vv.w;
            }
        }
        __syncthreads();
    }

    // ---- write y in (B, T, H*D) layout ----
    const int b = bh / HN, h = bh % HN;
    float inv = 1.f / lval;
    float* outp = g_y + ((size_t)b * TN + row_g) * DIMN + h * DH + half * 32;
#pragma unroll
    for (int j = 0; j < 8; ++j) {
        float4 t4;
        t4.x = acc[4*j+0] * inv; t4.y = acc[4*j+1] * inv;
        t4.z = acc[4*j+2] * inv; t4.w = acc[4*j+3] * inv;
        reinterpret_cast<float4*>(outp)[j] = t4;
    }
}

// ---------------------------------------------------------------------------
// Projection GEMM: out = g_y (4096x768) @ W (768x768)
// Block: 128 threads, 64x64 tile, BK=16, thread tile 4x8.
// Grid: (DIM/64, B*T/64)
// ---------------------------------------------------------------------------
__global__ __launch_bounds__(128) void proj_kernel(
    const float* __restrict__ W, float* __restrict__ out)
{
    __shared__ float As[16][65];   // A transposed: As[k][m]
    __shared__ float Bs2[16][64];  // Bs2[k][n]

    const int tid = threadIdx.x;
    const int tx = tid & 7;        // col group: 8 cols
    const int ty = tid >> 3;       // row group: 4 rows
    const int m0 = blockIdx.y * 64;
    const int n0 = blockIdx.x * 64;

    float c[4][8];
#pragma unroll
    for (int i = 0; i < 4; ++i)
#pragma unroll
        for (int j = 0; j < 8; ++j) c[i][j] = 0.f;

    for (int k0 = 0; k0 < DIMN; k0 += 16) {
        // stage A tile (64x16) transposed
#pragma unroll
        for (int i = 0; i < 2; ++i) {
            int idx = tid + i * 128;          // 0..255 float4s
            int r = idx >> 2, c4 = idx & 3;
            float4 av = reinterpret_cast<const float4*>(
                g_y + (size_t)(m0 + r) * DIMN + k0)[c4];
            As[c4*4+0][r] = av.x;
            As[c4*4+1][r] = av.y;
            As[c4*4+2][r] = av.z;
            As[c4*4+3][r] = av.w;
        }
        // stage B tile (16x64)
#pragma unroll
        for (int i = 0; i < 2; ++i) {
            int idx = tid + i * 128;          // 0..255 float4s
            int r = idx >> 4, c4 = idx & 15;
            reinterpret_cast<float4*>(&Bs2[r][0])[c4] =
                reinterpret_cast<const float4*>(W + (size_t)(k0 + r) * DIMN + n0)[c4];
        }
        __syncthreads();

#pragma unroll
        for (int kk = 0; kk < 16; ++kk) {
            float a[4], bb[8];
#pragma unroll
            for (int i = 0; i < 4; ++i) a[i] = As[kk][ty * 4 + i];
#pragma unroll
            for (int j = 0; j < 8; ++j) bb[j] = Bs2[kk][tx * 8 + j];
#pragma unroll
            for (int i = 0; i < 4; ++i)
#pragma unroll
                for (int j = 0; j < 8; ++j) c[i][j] += a[i] * bb[j];
        }
        __syncthreads();
    }

#pragma unroll
    for (int i = 0; i < 4; ++i) {
        float* op = out + (size_t)(m0 + ty * 4 + i) * DIMN + n0 + tx * 8;
#pragma unroll
        for (int j = 0; j < 2; ++j) {
            float4 t4;
            t4.x = c[i][4*j+0]; t4.y = c[i][4*j+1];
            t4.z = c[i][4*j+2]; t4.w = c[i][4*j+3];
            reinterpret_cast<float4*>(op)[j] = t4;
        }
    }
}

extern "C" void kernel_launch(void* const* d_in, const int* in_sizes, int n_in,
                              void* d_out, int out_size)
{
    (void)in_sizes; (void)n_in; (void)out_size;
    const float* q    = (const float*)d_in[0];
    const float* k    = (const float*)d_in[1];
    const float* v    = (const float*)d_in[2];
    const float* bias = (const float*)d_in[3];
    const float* W    = (const float*)d_in[4];
    float* out = (float*)d_out;

    attn_kernel<<<dim3(TN / BM, BSZ * HN), 128>>>(q, k, v, bias);
    proj_kernel<<<dim3(DIMN / 64, (BSZ * TN) / 64), 128>>>(W, out);
}

// round 4
// speedup vs baseline: 2.2633x; 2.2633x over previous
#include <cuda_runtime.h>
#include <cstdint>

// ---------------------------------------------------------------------------
// Problem constants
// ---------------------------------------------------------------------------
#define BSZ  2
#define HN   12
#define TN   2048
#define DH   64
#define DIMN 768

#define QTIL 128   // q rows per block (8 warps x 16 rows)
#define KTIL 64    // keys per main-loop iteration

__device__ float g_y[BSZ * TN * DIMN];  // intermediate (B, T, H*D)

// ---------------------------------------------------------------------------
// bf16 split helpers (bit tricks; round-to-nearest via +0x8000)
// ---------------------------------------------------------------------------
__device__ __forceinline__ uint32_t bfhi(float x) {
    return (__float_as_uint(x) + 0x8000u) & 0xFFFF0000u;
}
// pack bf16(x0) (low half) and bf16(x1) (high half); also lo residual pair
__device__ __forceinline__ void split2(float x0, float x1, uint32_t& hp, uint32_t& lp) {
    uint32_t h0 = bfhi(x0), h1 = bfhi(x1);
    float l0 = x0 - __uint_as_float(h0);
    float l1 = x1 - __uint_as_float(h1);
    hp = (h0 >> 16) | h1;
    lp = (bfhi(l0) >> 16) | bfhi(l1);
}
// smem swizzle: conflict-free for frag loads (8 consecutive rows x 4 word cols)
__device__ __forceinline__ int fsw(int r) {
    return ((r & 7) << 2) ^ ((r >> 3) & 3);
}

__device__ __forceinline__ void mma16816(float* c,
    uint32_t a0, uint32_t a1, uint32_t a2, uint32_t a3, uint32_t b0, uint32_t b1) {
    asm volatile(
        "mma.sync.aligned.m16n8k16.row.col.f32.bf16.bf16.f32 "
        "{%0,%1,%2,%3}, {%4,%5,%6,%7}, {%8,%9}, {%0,%1,%2,%3};"
        : "+f"(c[0]), "+f"(c[1]), "+f"(c[2]), "+f"(c[3])
        : "r"(a0), "r"(a1), "r"(a2), "r"(a3), "r"(b0), "r"(b1));
}

// ---------------------------------------------------------------------------
// Flash attention, bf16 mma.sync 3-pass split, causal + additive bias.
// Block: 256 threads (8 warps, 16 q-rows each). Grid: (16, B*H).
// ---------------------------------------------------------------------------
__global__ __launch_bounds__(256) void attn_mma_kernel(
    const float* __restrict__ q, const float* __restrict__ k,
    const float* __restrict__ v, const float* __restrict__ bias)
{
    // pool layout (uint32 words, 32KB):
    //   [0   ..2047]  Kh   (64 keys x 32 words)      | Q hi during prologue
    //   [2048..4095]  Kl                             | Q hi (rows 64..127)
    //   [4096..6143]  Vth  (64 dims x 32 key-words)  | Q lo
    //   [6144..8191]  Vtl                            | Q lo (rows 64..127)
    __shared__ uint32_t pool[8192];

    const int tid  = threadIdx.x;
    const int wid  = tid >> 5;
    const int lane = tid & 31;
    const int gr   = lane >> 2;     // group row 0..7
    const int tc   = lane & 3;      // thread col 0..3
    const int qt   = gridDim.x - 1 - blockIdx.x;   // big tiles first
    const int bh   = blockIdx.y;
    const int q0   = qt * QTIL;
    const int r0   = wid * 16 + gr;
    const int row_g0 = q0 + r0;
    const int row_g1 = row_g0 + 8;

    // ---- prologue: stage Q (hi/lo) into pool, then load A-frags ----
    {
        const float* qp = q + ((size_t)bh * TN + q0) * DH;
#pragma unroll
        for (int i = 0; i < 8; ++i) {
            int idx = tid + i * 256;          // 2048 float4s = 128 rows x 16
            int r = idx >> 4, c = idx & 15;
            float4 x = reinterpret_cast<const float4*>(qp + (size_t)r * DH)[c];
            uint32_t h0, l0, h1, l1;
            split2(x.x, x.y, h0, l0);
            split2(x.z, x.w, h1, l1);
            int s = fsw(r);
            pool[r * 32 + ((2 * c) ^ s)]            = h0;
            pool[r * 32 + ((2 * c + 1) ^ s)]        = h1;
            pool[4096 + r * 32 + ((2 * c) ^ s)]     = l0;
            pool[4096 + r * 32 + ((2 * c + 1) ^ s)] = l1;
        }
    }
    __syncthreads();

    uint32_t qh[4][4], ql[4][4];
    {
        const int ra = r0, rb = r0 + 8;
        const int sa = fsw(ra), sb = fsw(rb);
#pragma unroll
        for (int s = 0; s < 4; ++s) {
            int w0 = tc + 8 * s, w1 = w0 + 4;
            qh[s][0] = pool[ra * 32 + (w0 ^ sa)];
            qh[s][1] = pool[rb * 32 + (w0 ^ sb)];
            qh[s][2] = pool[ra * 32 + (w1 ^ sa)];
            qh[s][3] = pool[rb * 32 + (w1 ^ sb)];
            ql[s][0] = pool[4096 + ra * 32 + (w0 ^ sa)];
            ql[s][1] = pool[4096 + rb * 32 + (w0 ^ sb)];
            ql[s][2] = pool[4096 + ra * 32 + (w1 ^ sa)];
            ql[s][3] = pool[4096 + rb * 32 + (w1 ^ sb)];
        }
    }
    __syncthreads();

    float O[8][4];
#pragma unroll
    for (int n = 0; n < 8; ++n)
#pragma unroll
        for (int i = 0; i < 4; ++i) O[n][i] = 0.f;
    float m0 = -1e30f, m1 = -1e30f, l0 = 0.f, l1 = 0.f;

    const float* b0p = bias + ((size_t)bh * TN + row_g0) * TN;
    const float* b1p = b0p + (size_t)8 * TN;

    const int nj = 2 * qt + 2;
    for (int j = 0; j < nj; ++j) {
        const int kv0 = j * KTIL;

        // ---- stage K (hi/lo), K-major, swizzled ----
        {
            const float* kp = k + ((size_t)bh * TN + kv0) * DH;
#pragma unroll
            for (int i = 0; i < 4; ++i) {
                int idx = tid + i * 256;      // 1024 float4s = 64 keys x 16
                int r = idx >> 4, c = idx & 15;
                float4 x = reinterpret_cast<const float4*>(kp + (size_t)r * DH)[c];
                uint32_t h0, lo0, h1, lo1;
                split2(x.x, x.y, h0, lo0);
                split2(x.z, x.w, h1, lo1);
                int s = fsw(r);
                pool[r * 32 + ((2 * c) ^ s)]            = h0;
                pool[r * 32 + ((2 * c + 1) ^ s)]        = h1;
                pool[2048 + r * 32 + ((2 * c) ^ s)]     = lo0;
                pool[2048 + r * 32 + ((2 * c + 1) ^ s)] = lo1;
            }
        }
        // ---- stage V transposed (hi/lo): Vt[dim][key-word] ----
        {
            const float* vp = v + ((size_t)bh * TN + kv0) * DH;
            const int d = tid & 63;
            const int s = fsw(d);
#pragma unroll
            for (int o2 = 0; o2 < 2; ++o2) {
                int o = (tid >> 6) + 4 * o2;      // key octet 0..7
                float vv[8];
#pragma unroll
                for (int jj = 0; jj < 8; ++jj)
                    vv[jj] = vp[(size_t)(8 * o + jj) * DH + d];
#pragma unroll
                for (int p2 = 0; p2 < 4; ++p2) {
                    uint32_t hp, lp;
                    split2(vv[2 * p2], vv[2 * p2 + 1], hp, lp);
                    pool[4096 + d * 32 + ((4 * o + p2) ^ s)] = hp;
                    pool[6144 + d * 32 + ((4 * o + p2) ^ s)] = lp;
                }
            }
        }
        __syncthreads();

        // ---- S = Q K^T (3-pass bf16) ----
        float S[8][4];
#pragma unroll
        for (int n = 0; n < 8; ++n)
#pragma unroll
            for (int i = 0; i < 4; ++i) S[n][i] = 0.f;

#pragma unroll
        for (int s = 0; s < 4; ++s) {
#pragma unroll
            for (int n = 0; n < 8; ++n) {
                int key = n * 8 + gr;
                int sw  = fsw(key);
                int w0  = tc + 8 * s, w1 = w0 + 4;
                uint32_t kb0 = pool[key * 32 + (w0 ^ sw)];
                uint32_t kb1 = pool[key * 32 + (w1 ^ sw)];
                uint32_t kc0 = pool[2048 + key * 32 + (w0 ^ sw)];
                uint32_t kc1 = pool[2048 + key * 32 + (w1 ^ sw)];
                mma16816(S[n], qh[s][0], qh[s][1], qh[s][2], qh[s][3], kb0, kb1);
                mma16816(S[n], qh[s][0], qh[s][1], qh[s][2], qh[s][3], kc0, kc1);
                mma16816(S[n], ql[s][0], ql[s][1], ql[s][2], ql[s][3], kb0, kb1);
            }
        }

        // ---- scale + bias + causal mask ----
        const bool domask = (j >= 2 * qt);
#pragma unroll
        for (int n = 0; n < 8; ++n) {
            int col = kv0 + 8 * n + 2 * tc;
            float2 bb0 = *reinterpret_cast<const float2*>(b0p + col);
            float2 bb1 = *reinterpret_cast<const float2*>(b1p + col);
            S[n][0] = fmaf(S[n][0], 0.125f, bb0.x);
            S[n][1] = fmaf(S[n][1], 0.125f, bb0.y);
            S[n][2] = fmaf(S[n][2], 0.125f, bb1.x);
            S[n][3] = fmaf(S[n][3], 0.125f, bb1.y);
            if (domask) {
                if (col     > row_g0) S[n][0] = -1e30f;
                if (col + 1 > row_g0) S[n][1] = -1e30f;
                if (col     > row_g1) S[n][2] = -1e30f;
                if (col + 1 > row_g1) S[n][3] = -1e30f;
            }
        }

        // ---- online softmax ----
        float t0 = -1e30f, t1 = -1e30f;
#pragma unroll
        for (int n = 0; n < 8; ++n) {
            t0 = fmaxf(t0, fmaxf(S[n][0], S[n][1]));
            t1 = fmaxf(t1, fmaxf(S[n][2], S[n][3]));
        }
        t0 = fmaxf(t0, __shfl_xor_sync(0xffffffffu, t0, 1));
        t0 = fmaxf(t0, __shfl_xor_sync(0xffffffffu, t0, 2));
        t1 = fmaxf(t1, __shfl_xor_sync(0xffffffffu, t1, 1));
        t1 = fmaxf(t1, __shfl_xor_sync(0xffffffffu, t1, 2));
        float mn0 = fmaxf(m0, t0), mn1 = fmaxf(m1, t1);
        float c0 = __expf(m0 - mn0), c1 = __expf(m1 - mn1);
        m0 = mn0; m1 = mn1;
        float ls0 = 0.f, ls1 = 0.f;
#pragma unroll
        for (int n = 0; n < 8; ++n) {
            S[n][0] = __expf(S[n][0] - m0); ls0 += S[n][0];
            S[n][1] = __expf(S[n][1] - m0); ls0 += S[n][1];
            S[n][2] = __expf(S[n][2] - m1); ls1 += S[n][2];
            S[n][3] = __expf(S[n][3] - m1); ls1 += S[n][3];
        }
        l0 = l0 * c0 + ls0;
        l1 = l1 * c1 + ls1;
#pragma unroll
        for (int n = 0; n < 8; ++n) {
            O[n][0] *= c0; O[n][1] *= c0;
            O[n][2] *= c1; O[n][3] *= c1;
        }

        // ---- O += P V (3-pass bf16); P C-frag -> A-frag in registers ----
#pragma unroll
        for (int s = 0; s < 4; ++s) {
            uint32_t ph0, ph1, ph2, ph3, pl0, pl1, pl2, pl3;
            split2(S[2 * s][0],     S[2 * s][1],     ph0, pl0);
            split2(S[2 * s][2],     S[2 * s][3],     ph1, pl1);
            split2(S[2 * s + 1][0], S[2 * s + 1][1], ph2, pl2);
            split2(S[2 * s + 1][2], S[2 * s + 1][3], ph3, pl3);
#pragma unroll
            for (int n = 0; n < 8; ++n) {
                int d  = n * 8 + gr;
                int sw = fsw(d);
                int w0 = tc + 8 * s, w1 = w0 + 4;
                uint32_t vh0 = pool[4096 + d * 32 + (w0 ^ sw)];
                uint32_t vh1 = pool[4096 + d * 32 + (w1 ^ sw)];
                uint32_t vl0 = pool[6144 + d * 32 + (w0 ^ sw)];
                uint32_t vl1 = pool[6144 + d * 32 + (w1 ^ sw)];
                mma16816(O[n], ph0, ph1, ph2, ph3, vh0, vh1);
                mma16816(O[n], ph0, ph1, ph2, ph3, vl0, vl1);
                mma16816(O[n], pl0, pl1, pl2, pl3, vh0, vh1);
            }
        }
        __syncthreads();
    }

    // ---- finalize: O / l -> g_y (B, T, H*D) ----
    l0 += __shfl_xor_sync(0xffffffffu, l0, 1);
    l0 += __shfl_xor_sync(0xffffffffu, l0, 2);
    l1 += __shfl_xor_sync(0xffffffffu, l1, 1);
    l1 += __shfl_xor_sync(0xffffffffu, l1, 2);
    float inv0 = 1.f / l0, inv1 = 1.f / l1;

    const int b = bh / HN, h = bh % HN;
    float* o0 = g_y + ((size_t)b * TN + row_g0) * DIMN + h * DH;
    float* o1 = g_y + ((size_t)b * TN + row_g1) * DIMN + h * DH;
#pragma unroll
    for (int n = 0; n < 8; ++n) {
        int col = 8 * n + 2 * tc;
        float2 w0, w1;
        w0.x = O[n][0] * inv0; w0.y = O[n][1] * inv0;
        w1.x = O[n][2] * inv1; w1.y = O[n][3] * inv1;
        *reinterpret_cast<float2*>(o0 + col) = w0;
        *reinterpret_cast<float2*>(o1 + col) = w1;
    }
}

// ---------------------------------------------------------------------------
// Projection GEMM: out = g_y (4096x768) @ W (768x768)   (known good)
// ---------------------------------------------------------------------------
__global__ __launch_bounds__(128) void proj_kernel(
    const float* __restrict__ W, float* __restrict__ out)
{
    __shared__ float As[16][65];
    __shared__ float Bs2[16][64];

    const int tid = threadIdx.x;
    const int tx = tid & 7;
    const int ty = tid >> 3;
    const int m0 = blockIdx.y * 64;
    const int n0 = blockIdx.x * 64;

    float c[4][8];
#pragma unroll
    for (int i = 0; i < 4; ++i)
#pragma unroll
        for (int j = 0; j < 8; ++j) c[i][j] = 0.f;

    for (int k0 = 0; k0 < DIMN; k0 += 16) {
#pragma unroll
        for (int i = 0; i < 2; ++i) {
            int idx = tid + i * 128;
            int r = idx >> 2, c4 = idx & 3;
            float4 av = reinterpret_cast<const float4*>(
                g_y + (size_t)(m0 + r) * DIMN + k0)[c4];
            As[c4*4+0][r] = av.x;
            As[c4*4+1][r] = av.y;
            As[c4*4+2][r] = av.z;
            As[c4*4+3][r] = av.w;
        }
#pragma unroll
        for (int i = 0; i < 2; ++i) {
            int idx = tid + i * 128;
            int r = idx >> 4, c4 = idx & 15;
            reinterpret_cast<float4*>(&Bs2[r][0])[c4] =
                reinterpret_cast<const float4*>(W + (size_t)(k0 + r) * DIMN + n0)[c4];
        }
        __syncthreads();

#pragma unroll
        for (int kk = 0; kk < 16; ++kk) {
            float a[4], bb[8];
#pragma unroll
            for (int i = 0; i < 4; ++i) a[i] = As[kk][ty * 4 + i];
#pragma unroll
            for (int j = 0; j < 8; ++j) bb[j] = Bs2[kk][tx * 8 + j];
#pragma unroll
            for (int i = 0; i < 4; ++i)
#pragma unroll
                for (int j = 0; j < 8; ++j) c[i][j] += a[i] * bb[j];
        }
        __syncthreads();
    }

#pragma unroll
    for (int i = 0; i < 4; ++i) {
        float* op = out + (size_t)(m0 + ty * 4 + i) * DIMN + n0 + tx * 8;
#pragma unroll
        for (int j = 0; j < 2; ++j) {
            float4 t4;
            t4.x = c[i][4*j+0]; t4.y = c[i][4*j+1];
            t4.z = c[i][4*j+2]; t4.w = c[i][4*j+3];
            reinterpret_cast<float4*>(op)[j] = t4;
        }
    }
}

extern "C" void kernel_launch(void* const* d_in, const int* in_sizes, int n_in,
                              void* d_out, int out_size)
{
    (void)in_sizes; (void)n_in; (void)out_size;
    const float* q    = (const float*)d_in[0];
    const float* k    = (const float*)d_in[1];
    const float* v    = (const float*)d_in[2];
    const float* bias = (const float*)d_in[3];
    const float* W    = (const float*)d_in[4];
    float* out = (float*)d_out;

    attn_mma_kernel<<<dim3(TN / QTIL, BSZ * HN), 256>>>(q, k, v, bias);
    proj_kernel<<<dim3(DIMN / 64, (BSZ * TN) / 64), 128>>>(W, out);
}

// round 5
// speedup vs baseline: 3.1721x; 1.4015x over previous
#include <cuda_runtime.h>
#include <cstdint>

// ---------------------------------------------------------------------------
// Problem constants
// ---------------------------------------------------------------------------
#define BSZ  2
#define HN   12
#define TN   2048
#define DH   64
#define DIMN 768

#define QTIL 128   // q rows per block (8 warps x 16 rows)
#define KTIL 64    // keys per main-loop iteration

__device__ float g_y[BSZ * TN * DIMN];  // intermediate (B, T, H*D)

// ---------------------------------------------------------------------------
// bf16 split helpers (bit tricks; round-to-nearest via +0x8000)
// ---------------------------------------------------------------------------
__device__ __forceinline__ uint32_t bfhi(float x) {
    return (__float_as_uint(x) + 0x8000u) & 0xFFFF0000u;
}
// pack bf16(x0) (low half) and bf16(x1) (high half); also lo residual pair
__device__ __forceinline__ void split2(float x0, float x1, uint32_t& hp, uint32_t& lp) {
    uint32_t h0 = bfhi(x0), h1 = bfhi(x1);
    float l0 = x0 - __uint_as_float(h0);
    float l1 = x1 - __uint_as_float(h1);
    hp = (h0 >> 16) | h1;
    lp = (bfhi(l0) >> 16) | bfhi(l1);
}
// smem swizzle: conflict-free for frag loads (8 consecutive rows x 4 word cols)
__device__ __forceinline__ int fsw(int r) {
    return ((r & 7) << 2) ^ ((r >> 3) & 3);
}

__device__ __forceinline__ void mma16816(float* c,
    uint32_t a0, uint32_t a1, uint32_t a2, uint32_t a3, uint32_t b0, uint32_t b1) {
    asm volatile(
        "mma.sync.aligned.m16n8k16.row.col.f32.bf16.bf16.f32 "
        "{%0,%1,%2,%3}, {%4,%5,%6,%7}, {%8,%9}, {%0,%1,%2,%3};"
        : "+f"(c[0]), "+f"(c[1]), "+f"(c[2]), "+f"(c[3])
        : "r"(a0), "r"(a1), "r"(a2), "r"(a3), "r"(b0), "r"(b1));
}

// ---------------------------------------------------------------------------
// Flash attention, bf16 mma.sync 3-pass split, causal + additive bias.
// Block: 256 threads (8 warps, 16 q-rows each). Grid: (16, B*H).
// (unchanged from the passing round-4 kernel)
// ---------------------------------------------------------------------------
__global__ __launch_bounds__(256) void attn_mma_kernel(
    const float* __restrict__ q, const float* __restrict__ k,
    const float* __restrict__ v, const float* __restrict__ bias)
{
    __shared__ uint32_t pool[8192];

    const int tid  = threadIdx.x;
    const int wid  = tid >> 5;
    const int lane = tid & 31;
    const int gr   = lane >> 2;
    const int tc   = lane & 3;
    const int qt   = gridDim.x - 1 - blockIdx.x;   // big tiles first
    const int bh   = blockIdx.y;
    const int q0   = qt * QTIL;
    const int r0   = wid * 16 + gr;
    const int row_g0 = q0 + r0;
    const int row_g1 = row_g0 + 8;

    // ---- prologue: stage Q (hi/lo) into pool, then load A-frags ----
    {
        const float* qp = q + ((size_t)bh * TN + q0) * DH;
#pragma unroll
        for (int i = 0; i < 8; ++i) {
            int idx = tid + i * 256;
            int r = idx >> 4, c = idx & 15;
            float4 x = reinterpret_cast<const float4*>(qp + (size_t)r * DH)[c];
            uint32_t h0, l0, h1, l1;
            split2(x.x, x.y, h0, l0);
            split2(x.z, x.w, h1, l1);
            int s = fsw(r);
            pool[r * 32 + ((2 * c) ^ s)]            = h0;
            pool[r * 32 + ((2 * c + 1) ^ s)]        = h1;
            pool[4096 + r * 32 + ((2 * c) ^ s)]     = l0;
            pool[4096 + r * 32 + ((2 * c + 1) ^ s)] = l1;
        }
    }
    __syncthreads();

    uint32_t qh[4][4], ql[4][4];
    {
        const int ra = r0, rb = r0 + 8;
        const int sa = fsw(ra), sb = fsw(rb);
#pragma unroll
        for (int s = 0; s < 4; ++s) {
            int w0 = tc + 8 * s, w1 = w0 + 4;
            qh[s][0] = pool[ra * 32 + (w0 ^ sa)];
            qh[s][1] = pool[rb * 32 + (w0 ^ sb)];
            qh[s][2] = pool[ra * 32 + (w1 ^ sa)];
            qh[s][3] = pool[rb * 32 + (w1 ^ sb)];
            ql[s][0] = pool[4096 + ra * 32 + (w0 ^ sa)];
            ql[s][1] = pool[4096 + rb * 32 + (w0 ^ sb)];
            ql[s][2] = pool[4096 + ra * 32 + (w1 ^ sa)];
            ql[s][3] = pool[4096 + rb * 32 + (w1 ^ sb)];
        }
    }
    __syncthreads();

    float O[8][4];
#pragma unroll
    for (int n = 0; n < 8; ++n)
#pragma unroll
        for (int i = 0; i < 4; ++i) O[n][i] = 0.f;
    float m0 = -1e30f, m1 = -1e30f, l0 = 0.f, l1 = 0.f;

    const float* b0p = bias + ((size_t)bh * TN + row_g0) * TN;
    const float* b1p = b0p + (size_t)8 * TN;

    const int nj = 2 * qt + 2;
    for (int j = 0; j < nj; ++j) {
        const int kv0 = j * KTIL;

        // ---- stage K (hi/lo), K-major, swizzled ----
        {
            const float* kp = k + ((size_t)bh * TN + kv0) * DH;
#pragma unroll
            for (int i = 0; i < 4; ++i) {
                int idx = tid + i * 256;
                int r = idx >> 4, c = idx & 15;
                float4 x = reinterpret_cast<const float4*>(kp + (size_t)r * DH)[c];
                uint32_t h0, lo0, h1, lo1;
                split2(x.x, x.y, h0, lo0);
                split2(x.z, x.w, h1, lo1);
                int s = fsw(r);
                pool[r * 32 + ((2 * c) ^ s)]            = h0;
                pool[r * 32 + ((2 * c + 1) ^ s)]        = h1;
                pool[2048 + r * 32 + ((2 * c) ^ s)]     = lo0;
                pool[2048 + r * 32 + ((2 * c + 1) ^ s)] = lo1;
            }
        }
        // ---- stage V transposed (hi/lo): Vt[dim][key-word] ----
        {
            const float* vp = v + ((size_t)bh * TN + kv0) * DH;
            const int d = tid & 63;
            const int s = fsw(d);
#pragma unroll
            for (int o2 = 0; o2 < 2; ++o2) {
                int o = (tid >> 6) + 4 * o2;
                float vv[8];
#pragma unroll
                for (int jj = 0; jj < 8; ++jj)
                    vv[jj] = vp[(size_t)(8 * o + jj) * DH + d];
#pragma unroll
                for (int p2 = 0; p2 < 4; ++p2) {
                    uint32_t hp, lp;
                    split2(vv[2 * p2], vv[2 * p2 + 1], hp, lp);
                    pool[4096 + d * 32 + ((4 * o + p2) ^ s)] = hp;
                    pool[6144 + d * 32 + ((4 * o + p2) ^ s)] = lp;
                }
            }
        }
        __syncthreads();

        // ---- S = Q K^T (3-pass bf16) ----
        float S[8][4];
#pragma unroll
        for (int n = 0; n < 8; ++n)
#pragma unroll
            for (int i = 0; i < 4; ++i) S[n][i] = 0.f;

#pragma unroll
        for (int s = 0; s < 4; ++s) {
#pragma unroll
            for (int n = 0; n < 8; ++n) {
                int key = n * 8 + gr;
                int sw  = fsw(key);
                int w0  = tc + 8 * s, w1 = w0 + 4;
                uint32_t kb0 = pool[key * 32 + (w0 ^ sw)];
                uint32_t kb1 = pool[key * 32 + (w1 ^ sw)];
                uint32_t kc0 = pool[2048 + key * 32 + (w0 ^ sw)];
                uint32_t kc1 = pool[2048 + key * 32 + (w1 ^ sw)];
                mma16816(S[n], qh[s][0], qh[s][1], qh[s][2], qh[s][3], kb0, kb1);
                mma16816(S[n], qh[s][0], qh[s][1], qh[s][2], qh[s][3], kc0, kc1);
                mma16816(S[n], ql[s][0], ql[s][1], ql[s][2], ql[s][3], kb0, kb1);
            }
        }

        // ---- scale + bias + causal mask ----
        const bool domask = (j >= 2 * qt);
#pragma unroll
        for (int n = 0; n < 8; ++n) {
            int col = kv0 + 8 * n + 2 * tc;
            float2 bb0 = *reinterpret_cast<const float2*>(b0p + col);
            float2 bb1 = *reinterpret_cast<const float2*>(b1p + col);
            S[n][0] = fmaf(S[n][0], 0.125f, bb0.x);
            S[n][1] = fmaf(S[n][1], 0.125f, bb0.y);
            S[n][2] = fmaf(S[n][2], 0.125f, bb1.x);
            S[n][3] = fmaf(S[n][3], 0.125f, bb1.y);
            if (domask) {
                if (col     > row_g0) S[n][0] = -1e30f;
                if (col + 1 > row_g0) S[n][1] = -1e30f;
                if (col     > row_g1) S[n][2] = -1e30f;
                if (col + 1 > row_g1) S[n][3] = -1e30f;
            }
        }

        // ---- online softmax ----
        float t0 = -1e30f, t1 = -1e30f;
#pragma unroll
        for (int n = 0; n < 8; ++n) {
            t0 = fmaxf(t0, fmaxf(S[n][0], S[n][1]));
            t1 = fmaxf(t1, fmaxf(S[n][2], S[n][3]));
        }
        t0 = fmaxf(t0, __shfl_xor_sync(0xffffffffu, t0, 1));
        t0 = fmaxf(t0, __shfl_xor_sync(0xffffffffu, t0, 2));
        t1 = fmaxf(t1, __shfl_xor_sync(0xffffffffu, t1, 1));
        t1 = fmaxf(t1, __shfl_xor_sync(0xffffffffu, t1, 2));
        float mn0 = fmaxf(m0, t0), mn1 = fmaxf(m1, t1);
        float c0 = __expf(m0 - mn0), c1 = __expf(m1 - mn1);
        m0 = mn0; m1 = mn1;
        float ls0 = 0.f, ls1 = 0.f;
#pragma unroll
        for (int n = 0; n < 8; ++n) {
            S[n][0] = __expf(S[n][0] - m0); ls0 += S[n][0];
            S[n][1] = __expf(S[n][1] - m0); ls0 += S[n][1];
            S[n][2] = __expf(S[n][2] - m1); ls1 += S[n][2];
            S[n][3] = __expf(S[n][3] - m1); ls1 += S[n][3];
        }
        l0 = l0 * c0 + ls0;
        l1 = l1 * c1 + ls1;
#pragma unroll
        for (int n = 0; n < 8; ++n) {
            O[n][0] *= c0; O[n][1] *= c0;
            O[n][2] *= c1; O[n][3] *= c1;
        }

        // ---- O += P V (3-pass bf16); P C-frag -> A-frag in registers ----
#pragma unroll
        for (int s = 0; s < 4; ++s) {
            uint32_t ph0, ph1, ph2, ph3, pl0, pl1, pl2, pl3;
            split2(S[2 * s][0],     S[2 * s][1],     ph0, pl0);
            split2(S[2 * s][2],     S[2 * s][3],     ph1, pl1);
            split2(S[2 * s + 1][0], S[2 * s + 1][1], ph2, pl2);
            split2(S[2 * s + 1][2], S[2 * s + 1][3], ph3, pl3);
#pragma unroll
            for (int n = 0; n < 8; ++n) {
                int d  = n * 8 + gr;
                int sw = fsw(d);
                int w0 = tc + 8 * s, w1 = w0 + 4;
                uint32_t vh0 = pool[4096 + d * 32 + (w0 ^ sw)];
                uint32_t vh1 = pool[4096 + d * 32 + (w1 ^ sw)];
                uint32_t vl0 = pool[6144 + d * 32 + (w0 ^ sw)];
                uint32_t vl1 = pool[6144 + d * 32 + (w1 ^ sw)];
                mma16816(O[n], ph0, ph1, ph2, ph3, vh0, vh1);
                mma16816(O[n], ph0, ph1, ph2, ph3, vl0, vl1);
                mma16816(O[n], pl0, pl1, pl2, pl3, vh0, vh1);
            }
        }
        __syncthreads();
    }

    // ---- finalize: O / l -> g_y (B, T, H*D) ----
    l0 += __shfl_xor_sync(0xffffffffu, l0, 1);
    l0 += __shfl_xor_sync(0xffffffffu, l0, 2);
    l1 += __shfl_xor_sync(0xffffffffu, l1, 1);
    l1 += __shfl_xor_sync(0xffffffffu, l1, 2);
    float inv0 = 1.f / l0, inv1 = 1.f / l1;

    const int b = bh / HN, h = bh % HN;
    float* o0 = g_y + ((size_t)b * TN + row_g0) * DIMN + h * DH;
    float* o1 = g_y + ((size_t)b * TN + row_g1) * DIMN + h * DH;
#pragma unroll
    for (int n = 0; n < 8; ++n) {
        int col = 8 * n + 2 * tc;
        float2 w0, w1;
        w0.x = O[n][0] * inv0; w0.y = O[n][1] * inv0;
        w1.x = O[n][2] * inv1; w1.y = O[n][3] * inv1;
        *reinterpret_cast<float2*>(o0 + col) = w0;
        *reinterpret_cast<float2*>(o1 + col) = w1;
    }
}

// ---------------------------------------------------------------------------
// Projection GEMM via mma.sync bf16 3-pass: out = g_y (4096x768) @ W (768x768)
// Block: 256 threads (8 warps = 4M x 2N), 128x128 tile, K-chunk 64.
// Grid: (DIMN/128, B*T/128) = (6, 32)
// ---------------------------------------------------------------------------
__global__ __launch_bounds__(256) void proj_mma_kernel(
    const float* __restrict__ W, float* __restrict__ out)
{
    // dynamic pool (uint32 words, 64KB):
    //   [0    .. 4095]  Ah  (128 rows x 32 k-words)
    //   [4096 .. 8191]  Al
    //   [8192 ..12287]  Bth (128 n-rows x 32 k-words)  = W^T hi
    //   [12288..16383]  Btl
    extern __shared__ uint32_t pp[];

    const int tid  = threadIdx.x;
    const int wid  = tid >> 5;
    const int lane = tid & 31;
    const int gr   = lane >> 2;
    const int tc   = lane & 3;
    const int m_blk = blockIdx.y * 128;
    const int n_blk = blockIdx.x * 128;
    const int wm = (wid >> 1) * 32;    // warp row offset within tile
    const int wn = (wid & 1) * 64;     // warp col offset within tile

    float C[2][8][4];
#pragma unroll
    for (int mi = 0; mi < 2; ++mi)
#pragma unroll
        for (int n = 0; n < 8; ++n)
#pragma unroll
            for (int i = 0; i < 4; ++i) C[mi][n][i] = 0.f;

    for (int k0 = 0; k0 < DIMN; k0 += 64) {
        // ---- stage A = g_y tile (128 x 64), hi/lo, swizzled ----
        {
            const float* ap = g_y + (size_t)m_blk * DIMN + k0;
#pragma unroll
            for (int i = 0; i < 8; ++i) {
                int idx = tid + i * 256;      // 2048 float4s = 128 rows x 16
                int r = idx >> 4, c = idx & 15;
                float4 x = reinterpret_cast<const float4*>(ap + (size_t)r * DIMN)[c];
                uint32_t h0, l0, h1, l1;
                split2(x.x, x.y, h0, l0);
                split2(x.z, x.w, h1, l1);
                int s = fsw(r);
                pp[r * 32 + ((2 * c) ^ s)]            = h0;
                pp[r * 32 + ((2 * c + 1) ^ s)]        = h1;
                pp[4096 + r * 32 + ((2 * c) ^ s)]     = l0;
                pp[4096 + r * 32 + ((2 * c + 1) ^ s)] = l1;
            }
        }
        // ---- stage Bt = W^T tile: Bt[n (128)][k-words (32)], hi/lo ----
        {
            const int d = tid & 127;          // n index
            const int hf = tid >> 7;          // 0..1
            const int s = fsw(d);
            const float* wp = W + (size_t)k0 * DIMN + n_blk + d;
#pragma unroll
            for (int oo = 0; oo < 4; ++oo) {
                int o = hf + 2 * oo;          // k-octet 0..7
                float w8[8];
#pragma unroll
                for (int jj = 0; jj < 8; ++jj)
                    w8[jj] = wp[(size_t)(8 * o + jj) * DIMN];
#pragma unroll
                for (int p2 = 0; p2 < 4; ++p2) {
                    uint32_t hp, lp;
                    split2(w8[2 * p2], w8[2 * p2 + 1], hp, lp);
                    pp[8192  + d * 32 + ((4 * o + p2) ^ s)] = hp;
                    pp[12288 + d * 32 + ((4 * o + p2) ^ s)] = lp;
                }
            }
        }
        __syncthreads();

        // ---- 4 k16-steps ----
#pragma unroll
        for (int s = 0; s < 4; ++s) {
            const int w0 = tc + 8 * s, w1 = w0 + 4;
            uint32_t ah[2][4], al[2][4];
#pragma unroll
            for (int mi = 0; mi < 2; ++mi) {
                int ra = wm + 16 * mi + gr, rb = ra + 8;
                int sa = fsw(ra), sb = fsw(rb);
                ah[mi][0] = pp[ra * 32 + (w0 ^ sa)];
                ah[mi][1] = pp[rb * 32 + (w0 ^ sb)];
                ah[mi][2] = pp[ra * 32 + (w1 ^ sa)];
                ah[mi][3] = pp[rb * 32 + (w1 ^ sb)];
                al[mi][0] = pp[4096 + ra * 32 + (w0 ^ sa)];
                al[mi][1] = pp[4096 + rb * 32 + (w0 ^ sb)];
                al[mi][2] = pp[4096 + ra * 32 + (w1 ^ sa)];
                al[mi][3] = pp[4096 + rb * 32 + (w1 ^ sb)];
            }
#pragma unroll
            for (int n = 0; n < 8; ++n) {
                int br = wn + 8 * n + gr;
                int sw = fsw(br);
                uint32_t bh0 = pp[8192  + br * 32 + (w0 ^ sw)];
                uint32_t bh1 = pp[8192  + br * 32 + (w1 ^ sw)];
                uint32_t bl0 = pp[12288 + br * 32 + (w0 ^ sw)];
                uint32_t bl1 = pp[12288 + br * 32 + (w1 ^ sw)];
#pragma unroll
                for (int mi = 0; mi < 2; ++mi) {
                    mma16816(C[mi][n], ah[mi][0], ah[mi][1], ah[mi][2], ah[mi][3], bh0, bh1);
                    mma16816(C[mi][n], ah[mi][0], ah[mi][1], ah[mi][2], ah[mi][3], bl0, bl1);
                    mma16816(C[mi][n], al[mi][0], al[mi][1], al[mi][2], al[mi][3], bh0, bh1);
                }
            }
        }
        __syncthreads();
    }

    // ---- write C ----
#pragma unroll
    for (int mi = 0; mi < 2; ++mi) {
        int row0 = m_blk + wm + 16 * mi + gr;
        int row1 = row0 + 8;
#pragma unroll
        for (int n = 0; n < 8; ++n) {
            int col = n_blk + wn + 8 * n + 2 * tc;
            float2 w0, w1;
            w0.x = C[mi][n][0]; w0.y = C[mi][n][1];
            w1.x = C[mi][n][2]; w1.y = C[mi][n][3];
            *reinterpret_cast<float2*>(out + (size_t)row0 * DIMN + col) = w0;
            *reinterpret_cast<float2*>(out + (size_t)row1 * DIMN + col) = w1;
        }
    }
}

extern "C" void kernel_launch(void* const* d_in, const int* in_sizes, int n_in,
                              void* d_out, int out_size)
{
    (void)in_sizes; (void)n_in; (void)out_size;
    const float* q    = (const float*)d_in[0];
    const float* k    = (const float*)d_in[1];
    const float* v    = (const float*)d_in[2];
    const float* bias = (const float*)d_in[3];
    const float* W    = (const float*)d_in[4];
    float* out = (float*)d_out;

    attn_mma_kernel<<<dim3(TN / QTIL, BSZ * HN), 256>>>(q, k, v, bias);

    const int PROJ_SMEM = 16384 * 4;   // 64KB
    cudaFuncSetAttribute(proj_mma_kernel,
                         cudaFuncAttributeMaxDynamicSharedMemorySize, PROJ_SMEM);
    proj_mma_kernel<<<dim3(DIMN / 128, (BSZ * TN) / 128), 256, PROJ_SMEM>>>(W, out);
}

// round 6
// speedup vs baseline: 3.9413x; 1.2425x over previous
#include <cuda_runtime.h>
#include <cstdint>

// ---------------------------------------------------------------------------
// Problem constants
// ---------------------------------------------------------------------------
#define BSZ  2
#define HN   12
#define TN   2048
#define DH   64
#define DIMN 768

#define QTIL 128   // q rows per block (8 warps x 16 rows)
#define KTIL 64    // keys per main-loop iteration

__device__ float g_y[BSZ * TN * DIMN];  // intermediate (B, T, H*D)

// ---------------------------------------------------------------------------
// bf16 split helpers (bit tricks; round-to-nearest via +0x8000)
// ---------------------------------------------------------------------------
__device__ __forceinline__ uint32_t bfhi(float x) {
    return (__float_as_uint(x) + 0x8000u) & 0xFFFF0000u;
}
__device__ __forceinline__ void split2(float x0, float x1, uint32_t& hp, uint32_t& lp) {
    uint32_t h0 = bfhi(x0), h1 = bfhi(x1);
    float l0 = x0 - __uint_as_float(h0);
    float l1 = x1 - __uint_as_float(h1);
    hp = (h0 >> 16) | h1;
    lp = (bfhi(l0) >> 16) | bfhi(l1);
}
// smem swizzle: conflict-free for frag loads (8 consecutive rows x 4 word cols)
__device__ __forceinline__ int fsw(int r) {
    return ((r & 7) << 2) ^ ((r >> 3) & 3);
}

__device__ __forceinline__ void mma16816(float* c,
    uint32_t a0, uint32_t a1, uint32_t a2, uint32_t a3, uint32_t b0, uint32_t b1) {
    asm volatile(
        "mma.sync.aligned.m16n8k16.row.col.f32.bf16.bf16.f32 "
        "{%0,%1,%2,%3}, {%4,%5,%6,%7}, {%8,%9}, {%0,%1,%2,%3};"
        : "+f"(c[0]), "+f"(c[1]), "+f"(c[2]), "+f"(c[3])
        : "r"(a0), "r"(a1), "r"(a2), "r"(a3), "r"(b0), "r"(b1));
}

__device__ __forceinline__ uint32_t smem_u32(const void* p) {
    uint32_t a;
    asm("{ .reg .u64 t; cvta.to.shared.u64 t, %1; cvt.u32.u64 %0, t; }" : "=r"(a) : "l"(p));
    return a;
}
__device__ __forceinline__ void cpasync16(uint32_t dst, const void* src) {
    asm volatile("cp.async.cg.shared.global [%0], [%1], 16;" :: "r"(dst), "l"(src));
}
#define CP_COMMIT() asm volatile("cp.async.commit_group;" ::: "memory")
#define CP_WAIT0()  asm volatile("cp.async.wait_group 0;" ::: "memory")

// ---------------------------------------------------------------------------
// Flash attention, bf16 mma.sync 3-pass, cp.async pipelined staging.
// Block: 256 threads (8 warps, 16 q-rows each). Grid: (16, B*H).
// Dynamic smem 64KB (u32 words):
//   [0    .. 2047]  Kh  | Q hi (prologue)
//   [2048 .. 4095]  Kl  | Q hi rows 64..127
//   [4096 .. 6143]  Vth | Q lo
//   [6144 .. 8191]  Vtl | Q lo rows 64..127
//   [8192 ..12287]  raw K tile (64x64 f32)
//   [12288..16383]  raw V tile (64x64 f32)
// ---------------------------------------------------------------------------
#define RAWK 8192
#define RAWV 12288
#define ATTN_SMEM (16384 * 4)

__global__ __launch_bounds__(256) void attn_mma_kernel(
    const float* __restrict__ q, const float* __restrict__ k,
    const float* __restrict__ v, const float* __restrict__ bias)
{
    extern __shared__ uint32_t pool[];

    const int tid  = threadIdx.x;
    const int wid  = tid >> 5;
    const int lane = tid & 31;
    const int gr   = lane >> 2;
    const int tc   = lane & 3;
    const int qt   = gridDim.x - 1 - blockIdx.x;   // big tiles first
    const int bh   = blockIdx.y;
    const int q0   = qt * QTIL;
    const int r0   = wid * 16 + gr;
    const int row_g0 = q0 + r0;
    const int row_g1 = row_g0 + 8;

    const uint32_t rawk_b = smem_u32(pool + RAWK);
    const uint32_t rawv_b = smem_u32(pool + RAWV);
    const float* kbase = k + (size_t)bh * TN * DH;
    const float* vbase = v + (size_t)bh * TN * DH;

    // ---- prologue: kick off cp.async for tile 0 ----
    {
        const float* kp = kbase;               // kv0 = 0
        const float* vp = vbase;
#pragma unroll
        for (int i = 0; i < 4; ++i) {
            int idx = tid + i * 256;           // 1024 16B chunks each
            cpasync16(rawk_b + idx * 16, kp + idx * 4);
            cpasync16(rawv_b + idx * 16, vp + idx * 4);
        }
        CP_COMMIT();
    }

    // ---- stage Q (hi/lo) into pool, then load A-frags ----
    {
        const float* qp = q + ((size_t)bh * TN + q0) * DH;
#pragma unroll
        for (int i = 0; i < 8; ++i) {
            int idx = tid + i * 256;
            int r = idx >> 4, c = idx & 15;
            float4 x = reinterpret_cast<const float4*>(qp + (size_t)r * DH)[c];
            uint32_t h0, l0, h1, l1;
            split2(x.x, x.y, h0, l0);
            split2(x.z, x.w, h1, l1);
            int s = fsw(r);
            pool[r * 32 + ((2 * c) ^ s)]            = h0;
            pool[r * 32 + ((2 * c + 1) ^ s)]        = h1;
            pool[4096 + r * 32 + ((2 * c) ^ s)]     = l0;
            pool[4096 + r * 32 + ((2 * c + 1) ^ s)] = l1;
        }
    }
    __syncthreads();

    uint32_t qh[4][4], ql[4][4];
    {
        const int ra = r0, rb = r0 + 8;
        const int sa = fsw(ra), sb = fsw(rb);
#pragma unroll
        for (int s = 0; s < 4; ++s) {
            int w0 = tc + 8 * s, w1 = w0 + 4;
            qh[s][0] = pool[ra * 32 + (w0 ^ sa)];
            qh[s][1] = pool[rb * 32 + (w0 ^ sb)];
            qh[s][2] = pool[ra * 32 + (w1 ^ sa)];
            qh[s][3] = pool[rb * 32 + (w1 ^ sb)];
            ql[s][0] = pool[4096 + ra * 32 + (w0 ^ sa)];
            ql[s][1] = pool[4096 + rb * 32 + (w0 ^ sb)];
            ql[s][2] = pool[4096 + ra * 32 + (w1 ^ sa)];
            ql[s][3] = pool[4096 + rb * 32 + (w1 ^ sb)];
        }
    }

    float O[8][4];
#pragma unroll
    for (int n = 0; n < 8; ++n)
#pragma unroll
        for (int i = 0; i < 4; ++i) O[n][i] = 0.f;
    float m0 = -1e30f, m1 = -1e30f, l0 = 0.f, l1 = 0.f;

    const float* b0p = bias + ((size_t)bh * TN + row_g0) * TN;
    const float* b1p = b0p + (size_t)8 * TN;

    const int nj = 2 * qt + 2;
    for (int j = 0; j < nj; ++j) {
        const int kv0 = j * KTIL;

        // ---- wait raw tile j; pool frags from tile j-1 already consumed ----
        CP_WAIT0();
        __syncthreads();

        // ---- split raw K -> Kh/Kl (swizzled) ----
        {
            const float4* kraw = reinterpret_cast<const float4*>(pool + RAWK);
#pragma unroll
            for (int i = 0; i < 4; ++i) {
                int idx = tid + i * 256;
                int r = idx >> 4, c = idx & 15;
                float4 x = kraw[idx];
                uint32_t h0, lo0, h1, lo1;
                split2(x.x, x.y, h0, lo0);
                split2(x.z, x.w, h1, lo1);
                int s = fsw(r);
                pool[r * 32 + ((2 * c) ^ s)]            = h0;
                pool[r * 32 + ((2 * c + 1) ^ s)]        = h1;
                pool[2048 + r * 32 + ((2 * c) ^ s)]     = lo0;
                pool[2048 + r * 32 + ((2 * c + 1) ^ s)] = lo1;
            }
        }
        // ---- split raw V (transposed) -> Vth/Vtl ----
        {
            const float* vraw = reinterpret_cast<const float*>(pool + RAWV);
            const int d = tid & 63;
            const int s = fsw(d);
#pragma unroll
            for (int o2 = 0; o2 < 2; ++o2) {
                int o = (tid >> 6) + 4 * o2;
                float vv[8];
#pragma unroll
                for (int jj = 0; jj < 8; ++jj)
                    vv[jj] = vraw[(8 * o + jj) * 64 + d];
#pragma unroll
                for (int p2 = 0; p2 < 4; ++p2) {
                    uint32_t hp, lp;
                    split2(vv[2 * p2], vv[2 * p2 + 1], hp, lp);
                    pool[4096 + d * 32 + ((4 * o + p2) ^ s)] = hp;
                    pool[6144 + d * 32 + ((4 * o + p2) ^ s)] = lp;
                }
            }
        }
        __syncthreads();   // splits visible; raw fully consumed

        // ---- kick off cp.async for tile j+1 (lands during mma) ----
        if (j + 1 < nj) {
            const float* kp = kbase + (size_t)(kv0 + KTIL) * DH;
            const float* vp = vbase + (size_t)(kv0 + KTIL) * DH;
#pragma unroll
            for (int i = 0; i < 4; ++i) {
                int idx = tid + i * 256;
                cpasync16(rawk_b + idx * 16, kp + idx * 4);
                cpasync16(rawv_b + idx * 16, vp + idx * 4);
            }
            CP_COMMIT();
        }

        // ---- prefetch bias into registers (consumed after QK mmas) ----
        float2 bb0r[8], bb1r[8];
#pragma unroll
        for (int n = 0; n < 8; ++n) {
            int col = kv0 + 8 * n + 2 * tc;
            bb0r[n] = *reinterpret_cast<const float2*>(b0p + col);
            bb1r[n] = *reinterpret_cast<const float2*>(b1p + col);
        }

        // ---- S = Q K^T (3-pass bf16) ----
        float S[8][4];
#pragma unroll
        for (int n = 0; n < 8; ++n)
#pragma unroll
            for (int i = 0; i < 4; ++i) S[n][i] = 0.f;

#pragma unroll
        for (int s = 0; s < 4; ++s) {
#pragma unroll
            for (int n = 0; n < 8; ++n) {
                int key = n * 8 + gr;
                int sw  = fsw(key);
                int w0  = tc + 8 * s, w1 = w0 + 4;
                uint32_t kb0 = pool[key * 32 + (w0 ^ sw)];
                uint32_t kb1 = pool[key * 32 + (w1 ^ sw)];
                uint32_t kc0 = pool[2048 + key * 32 + (w0 ^ sw)];
                uint32_t kc1 = pool[2048 + key * 32 + (w1 ^ sw)];
                mma16816(S[n], qh[s][0], qh[s][1], qh[s][2], qh[s][3], kb0, kb1);
                mma16816(S[n], qh[s][0], qh[s][1], qh[s][2], qh[s][3], kc0, kc1);
                mma16816(S[n], ql[s][0], ql[s][1], ql[s][2], ql[s][3], kb0, kb1);
            }
        }

        // ---- scale + bias + causal mask ----
        const bool domask = (j >= 2 * qt);
#pragma unroll
        for (int n = 0; n < 8; ++n) {
            int col = kv0 + 8 * n + 2 * tc;
            S[n][0] = fmaf(S[n][0], 0.125f, bb0r[n].x);
            S[n][1] = fmaf(S[n][1], 0.125f, bb0r[n].y);
            S[n][2] = fmaf(S[n][2], 0.125f, bb1r[n].x);
            S[n][3] = fmaf(S[n][3], 0.125f, bb1r[n].y);
            if (domask) {
                if (col     > row_g0) S[n][0] = -1e30f;
                if (col + 1 > row_g0) S[n][1] = -1e30f;
                if (col     > row_g1) S[n][2] = -1e30f;
                if (col + 1 > row_g1) S[n][3] = -1e30f;
            }
        }

        // ---- online softmax ----
        float t0 = -1e30f, t1 = -1e30f;
#pragma unroll
        for (int n = 0; n < 8; ++n) {
            t0 = fmaxf(t0, fmaxf(S[n][0], S[n][1]));
            t1 = fmaxf(t1, fmaxf(S[n][2], S[n][3]));
        }
        t0 = fmaxf(t0, __shfl_xor_sync(0xffffffffu, t0, 1));
        t0 = fmaxf(t0, __shfl_xor_sync(0xffffffffu, t0, 2));
        t1 = fmaxf(t1, __shfl_xor_sync(0xffffffffu, t1, 1));
        t1 = fmaxf(t1, __shfl_xor_sync(0xffffffffu, t1, 2));
        float mn0 = fmaxf(m0, t0), mn1 = fmaxf(m1, t1);
        float c0 = __expf(m0 - mn0), c1 = __expf(m1 - mn1);
        m0 = mn0; m1 = mn1;
        float ls0 = 0.f, ls1 = 0.f;
#pragma unroll
        for (int n = 0; n < 8; ++n) {
            S[n][0] = __expf(S[n][0] - m0); ls0 += S[n][0];
            S[n][1] = __expf(S[n][1] - m0); ls0 += S[n][1];
            S[n][2] = __expf(S[n][2] - m1); ls1 += S[n][2];
            S[n][3] = __expf(S[n][3] - m1); ls1 += S[n][3];
        }
        l0 = l0 * c0 + ls0;
        l1 = l1 * c1 + ls1;
#pragma unroll
        for (int n = 0; n < 8; ++n) {
            O[n][0] *= c0; O[n][1] *= c0;
            O[n][2] *= c1; O[n][3] *= c1;
        }

        // ---- O += P V (3-pass bf16); P C-frag -> A-frag in registers ----
#pragma unroll
        for (int s = 0; s < 4; ++s) {
            uint32_t ph0, ph1, ph2, ph3, pl0, pl1, pl2, pl3;
            split2(S[2 * s][0],     S[2 * s][1],     ph0, pl0);
            split2(S[2 * s][2],     S[2 * s][3],     ph1, pl1);
            split2(S[2 * s + 1][0], S[2 * s + 1][1], ph2, pl2);
            split2(S[2 * s + 1][2], S[2 * s + 1][3], ph3, pl3);
#pragma unroll
            for (int n = 0; n < 8; ++n) {
                int d  = n * 8 + gr;
                int sw = fsw(d);
                int w0 = tc + 8 * s, w1 = w0 + 4;
                uint32_t vh0 = pool[4096 + d * 32 + (w0 ^ sw)];
                uint32_t vh1 = pool[4096 + d * 32 + (w1 ^ sw)];
                uint32_t vl0 = pool[6144 + d * 32 + (w0 ^ sw)];
                uint32_t vl1 = pool[6144 + d * 32 + (w1 ^ sw)];
                mma16816(O[n], ph0, ph1, ph2, ph3, vh0, vh1);
                mma16816(O[n], ph0, ph1, ph2, ph3, vl0, vl1);
                mma16816(O[n], pl0, pl1, pl2, pl3, vh0, vh1);
            }
        }
        __syncthreads();   // PV reads done before next split overwrites pool
    }

    // ---- finalize: O / l -> g_y (B, T, H*D) ----
    l0 += __shfl_xor_sync(0xffffffffu, l0, 1);
    l0 += __shfl_xor_sync(0xffffffffu, l0, 2);
    l1 += __shfl_xor_sync(0xffffffffu, l1, 1);
    l1 += __shfl_xor_sync(0xffffffffu, l1, 2);
    float inv0 = 1.f / l0, inv1 = 1.f / l1;

    const int b = bh / HN, h = bh % HN;
    float* o0 = g_y + ((size_t)b * TN + row_g0) * DIMN + h * DH;
    float* o1 = g_y + ((size_t)b * TN + row_g1) * DIMN + h * DH;
#pragma unroll
    for (int n = 0; n < 8; ++n) {
        int col = 8 * n + 2 * tc;
        float2 w0, w1;
        w0.x = O[n][0] * inv0; w0.y = O[n][1] * inv0;
        w1.x = O[n][2] * inv1; w1.y = O[n][3] * inv1;
        *reinterpret_cast<float2*>(o0 + col) = w0;
        *reinterpret_cast<float2*>(o1 + col) = w1;
    }
}

// ---------------------------------------------------------------------------
// Projection GEMM via mma.sync bf16 3-pass (unchanged from round 5)
// ---------------------------------------------------------------------------
__global__ __launch_bounds__(256) void proj_mma_kernel(
    const float* __restrict__ W, float* __restrict__ out)
{
    extern __shared__ uint32_t pp[];

    const int tid  = threadIdx.x;
    const int wid  = tid >> 5;
    const int lane = tid & 31;
    const int gr   = lane >> 2;
    const int tc   = lane & 3;
    const int m_blk = blockIdx.y * 128;
    const int n_blk = blockIdx.x * 128;
    const int wm = (wid >> 1) * 32;
    const int wn = (wid & 1) * 64;

    float C[2][8][4];
#pragma unroll
    for (int mi = 0; mi < 2; ++mi)
#pragma unroll
        for (int n = 0; n < 8; ++n)
#pragma unroll
            for (int i = 0; i < 4; ++i) C[mi][n][i] = 0.f;

    for (int k0 = 0; k0 < DIMN; k0 += 64) {
        {
            const float* ap = g_y + (size_t)m_blk * DIMN + k0;
#pragma unroll
            for (int i = 0; i < 8; ++i) {
                int idx = tid + i * 256;
                int r = idx >> 4, c = idx & 15;
                float4 x = reinterpret_cast<const float4*>(ap + (size_t)r * DIMN)[c];
                uint32_t h0, l0, h1, l1;
                split2(x.x, x.y, h0, l0);
                split2(x.z, x.w, h1, l1);
                int s = fsw(r);
                pp[r * 32 + ((2 * c) ^ s)]            = h0;
                pp[r * 32 + ((2 * c + 1) ^ s)]        = h1;
                pp[4096 + r * 32 + ((2 * c) ^ s)]     = l0;
                pp[4096 + r * 32 + ((2 * c + 1) ^ s)] = l1;
            }
        }
        {
            const int d = tid & 127;
            const int hf = tid >> 7;
            const int s = fsw(d);
            const float* wp = W + (size_t)k0 * DIMN + n_blk + d;
#pragma unroll
            for (int oo = 0; oo < 4; ++oo) {
                int o = hf + 2 * oo;
                float w8[8];
#pragma unroll
                for (int jj = 0; jj < 8; ++jj)
                    w8[jj] = wp[(size_t)(8 * o + jj) * DIMN];
#pragma unroll
                for (int p2 = 0; p2 < 4; ++p2) {
                    uint32_t hp, lp;
                    split2(w8[2 * p2], w8[2 * p2 + 1], hp, lp);
                    pp[8192  + d * 32 + ((4 * o + p2) ^ s)] = hp;
                    pp[12288 + d * 32 + ((4 * o + p2) ^ s)] = lp;
                }
            }
        }
        __syncthreads();

#pragma unroll
        for (int s = 0; s < 4; ++s) {
            const int w0 = tc + 8 * s, w1 = w0 + 4;
            uint32_t ah[2][4], al[2][4];
#pragma unroll
            for (int mi = 0; mi < 2; ++mi) {
                int ra = wm + 16 * mi + gr, rb = ra + 8;
                int sa = fsw(ra), sb = fsw(rb);
                ah[mi][0] = pp[ra * 32 + (w0 ^ sa)];
                ah[mi][1] = pp[rb * 32 + (w0 ^ sb)];
                ah[mi][2] = pp[ra * 32 + (w1 ^ sa)];
                ah[mi][3] = pp[rb * 32 + (w1 ^ sb)];
                al[mi][0] = pp[4096 + ra * 32 + (w0 ^ sa)];
                al[mi][1] = pp[4096 + rb * 32 + (w0 ^ sb)];
                al[mi][2] = pp[4096 + ra * 32 + (w1 ^ sa)];
                al[mi][3] = pp[4096 + rb * 32 + (w1 ^ sb)];
            }
#pragma unroll
            for (int n = 0; n < 8; ++n) {
                int br = wn + 8 * n + gr;
                int sw = fsw(br);
                uint32_t bh0 = pp[8192  + br * 32 + (w0 ^ sw)];
                uint32_t bh1 = pp[8192  + br * 32 + (w1 ^ sw)];
                uint32_t bl0 = pp[12288 + br * 32 + (w0 ^ sw)];
                uint32_t bl1 = pp[12288 + br * 32 + (w1 ^ sw)];
#pragma unroll
                for (int mi = 0; mi < 2; ++mi) {
                    mma16816(C[mi][n], ah[mi][0], ah[mi][1], ah[mi][2], ah[mi][3], bh0, bh1);
                    mma16816(C[mi][n], ah[mi][0], ah[mi][1], ah[mi][2], ah[mi][3], bl0, bl1);
                    mma16816(C[mi][n], al[mi][0], al[mi][1], al[mi][2], al[mi][3], bh0, bh1);
                }
            }
        }
        __syncthreads();
    }

#pragma unroll
    for (int mi = 0; mi < 2; ++mi) {
        int row0 = m_blk + wm + 16 * mi + gr;
        int row1 = row0 + 8;
#pragma unroll
        for (int n = 0; n < 8; ++n) {
            int col = n_blk + wn + 8 * n + 2 * tc;
            float2 w0, w1;
            w0.x = C[mi][n][0]; w0.y = C[mi][n][1];
            w1.x = C[mi][n][2]; w1.y = C[mi][n][3];
            *reinterpret_cast<float2*>(out + (size_t)row0 * DIMN + col) = w0;
            *reinterpret_cast<float2*>(out + (size_t)row1 * DIMN + col) = w1;
        }
    }
}

extern "C" void kernel_launch(void* const* d_in, const int* in_sizes, int n_in,
                              void* d_out, int out_size)
{
    (void)in_sizes; (void)n_in; (void)out_size;
    const float* q    = (const float*)d_in[0];
    const float* k    = (const float*)d_in[1];
    const float* v    = (const float*)d_in[2];
    const float* bias = (const float*)d_in[3];
    const float* W    = (const float*)d_in[4];
    float* out = (float*)d_out;

    cudaFuncSetAttribute(attn_mma_kernel,
                         cudaFuncAttributeMaxDynamicSharedMemorySize, ATTN_SMEM);
    attn_mma_kernel<<<dim3(TN / QTIL, BSZ * HN), 256, ATTN_SMEM>>>(q, k, v, bias);

    const int PROJ_SMEM = 16384 * 4;   // 64KB
    cudaFuncSetAttribute(proj_mma_kernel,
                         cudaFuncAttributeMaxDynamicSharedMemorySize, PROJ_SMEM);
    proj_mma_kernel<<<dim3(DIMN / 128, (BSZ * TN) / 128), 256, PROJ_SMEM>>>(W, out);
}